// round 9
// baseline (speedup 1.0000x reference)
#include <cuda_runtime.h>

// Problem constants
#define B_     256
#define C_IN_  8
#define N_     4096
#define K_     9
#define S_     2
#define C_OUT_ 8

#define NB_    (N_ * B_)

#define WPAIRS_PER_CK 4    // C_OUT/2 f32x2 pairs per (s,c,k)
#define WPAIRS_PER_S  (C_IN_ * K_ * WPAIRS_PER_CK)   // 288
#define W_ELEMS       (S_ * C_IN_ * K_ * C_OUT_)     // 1152 floats

// Main-kernel tiling: 8 n x 128 b per block; warp = 1 n x 128 b (4 b per lane)
#define NT  8
#define BT  128
#define SOUT_STRIDE 130   // even, ≡2 mod 32: conflict-free staging, ≤2-way epilogue

// Scratch (device global: allocation-free rule)
__device__ float g_xT[C_IN_ * N_ * B_];     // (c, n, b)  33.5 MB

__device__ __forceinline__ unsigned long long splat2(float v) {
    unsigned long long r;
    asm("mov.b64 %0, {%1, %1};" : "=l"(r) : "f"(v));
    return r;
}
__device__ __forceinline__ void fma2(unsigned long long& acc,
                                     unsigned long long a,
                                     unsigned long long b) {
    asm("fma.rn.f32x2 %0, %1, %2, %0;" : "+l"(acc) : "l"(a), "l"(b));
}
__device__ __forceinline__ void unpack2(unsigned long long v, float& lo, float& hi) {
    asm("mov.b64 {%0, %1}, %2;" : "=f"(lo), "=f"(hi) : "l"(v));
}

// ---------------------------------------------------------------------------
// K1: x (B, C_IN, N) -> g_xT (C_IN, N, B). float4 both directions.
// ---------------------------------------------------------------------------
__global__ __launch_bounds__(256) void transpose_x_kernel(const float* __restrict__ x)
{
    __shared__ float tile[128][33];
    const int c  = blockIdx.z;
    const int n0 = blockIdx.x * 128;
    const int b0 = blockIdx.y * 32;
    const int tx = threadIdx.x;      // 0..31
    const int ty = threadIdx.y;      // 0..7

    #pragma unroll
    for (int j = 0; j < 4; ++j) {
        const int b = ty + 8 * j;
        const float4 v = *reinterpret_cast<const float4*>(
            x + ((size_t)(b0 + b) * C_IN_ + c) * N_ + n0 + 4 * tx);
        tile[4 * tx + 0][b] = v.x;
        tile[4 * tx + 1][b] = v.y;
        tile[4 * tx + 2][b] = v.z;
        tile[4 * tx + 3][b] = v.w;
    }
    __syncthreads();

    const int tid = ty * 32 + tx;
    #pragma unroll
    for (int j = 0; j < 4; ++j) {
        const int g = j * 256 + tid;
        const int n = g >> 3;
        const int q = g & 7;
        float4 v;
        v.x = tile[n][4 * q + 0];
        v.y = tile[n][4 * q + 1];
        v.z = tile[n][4 * q + 2];
        v.w = tile[n][4 * q + 3];
        *reinterpret_cast<float4*>(
            g_xT + ((size_t)c * N_ + n0 + n) * B_ + b0 + 4 * q) = v;
    }
}

// ---------------------------------------------------------------------------
// K2: fused main compute + output transpose.
// Warp = 1 n x 128 b (float4 gather, weight LDS amortized over 128 b),
// k-outer / c-inner loop for the register diet (single scalar neighbor
// offset live), targeting <=64 regs with NO spills at 4 CTAs/SM.
// grid (N/8, B/128) = 1024 blocks.
// ---------------------------------------------------------------------------
__global__ __launch_bounds__(256, 4)
void lattice_main_kernel(const int*   __restrict__ nbr,
                         const int*   __restrict__ sub_ids,
                         const float* __restrict__ weight,
                         const float* __restrict__ bias,
                         float*       __restrict__ out)
{
    __shared__ __align__(16) unsigned long long sw[S_ * WPAIRS_PER_S]; // 4608 B
    __shared__ __align__(16) unsigned long long sb[S_ * WPAIRS_PER_CK];
    __shared__ float sout[C_OUT_][NT][SOUT_STRIDE];                     // 33.3 KB

    const int tid  = threadIdx.x;
    const int lane = tid & 31;
    const int wid  = tid >> 5;

    {   // weight layout (s,c,k,d) is d-innermost -> raw copy = packed f32x2
        float* swf = reinterpret_cast<float*>(sw);
        #pragma unroll
        for (int i = tid; i < W_ELEMS; i += 256) swf[i] = weight[i];
        float* sbf = reinterpret_cast<float*>(sb);
        if (tid < S_ * C_OUT_) sbf[tid] = bias[tid];
    }
    __syncthreads();

    const int n0 = blockIdx.x * NT;
    const int b0 = blockIdx.y * BT;
    const float* xb = g_xT + b0 + 4 * lane;

    {
        const int n = n0 + wid;
        const int s = __ldg(&sub_ids[n]);   // uniform across warp

        // acc[j][m]: d-pair j (d = 2j, 2j+1), b offset m (b = b0 + 4*lane + m)
        unsigned long long acc[4][4];
        #pragma unroll
        for (int j = 0; j < 4; ++j) {
            const unsigned long long bj = sb[s * WPAIRS_PER_CK + j];
            #pragma unroll
            for (int m = 0; m < 4; ++m) acc[j][m] = bj;
        }

        const unsigned long long* wrow = sw + s * WPAIRS_PER_S;

        #pragma unroll
        for (int k = 0; k < K_; ++k) {
            // Single scalar neighbor offset live per k (register diet).
            const int ro = __ldg(&nbr[n * K_ + k]) * B_;   // uniform
            const float* xk = xb + ro;
            const unsigned long long* wk = wrow + k * WPAIRS_PER_CK;

            #pragma unroll
            for (int c = 0; c < C_IN_; ++c) {
                const float4 xv = __ldg(reinterpret_cast<const float4*>(
                    xk + (size_t)c * NB_));
                const unsigned long long x0 = splat2(xv.x);
                const unsigned long long x1 = splat2(xv.y);
                const unsigned long long x2 = splat2(xv.z);
                const unsigned long long x3 = splat2(xv.w);
                const unsigned long long* w4 = wk + c * (K_ * WPAIRS_PER_CK);
                const ulonglong2 wa = *reinterpret_cast<const ulonglong2*>(w4);     // bcast
                const ulonglong2 wb = *reinterpret_cast<const ulonglong2*>(w4 + 2); // bcast
                fma2(acc[0][0], x0, wa.x); fma2(acc[0][1], x1, wa.x);
                fma2(acc[0][2], x2, wa.x); fma2(acc[0][3], x3, wa.x);
                fma2(acc[1][0], x0, wa.y); fma2(acc[1][1], x1, wa.y);
                fma2(acc[1][2], x2, wa.y); fma2(acc[1][3], x3, wa.y);
                fma2(acc[2][0], x0, wb.x); fma2(acc[2][1], x1, wb.x);
                fma2(acc[2][2], x2, wb.x); fma2(acc[2][3], x3, wb.x);
                fma2(acc[3][0], x0, wb.y); fma2(acc[3][1], x1, wb.y);
                fma2(acc[3][2], x2, wb.y); fma2(acc[3][3], x3, wb.y);
            }
        }

        // Stage: scalar stores, lanes stride-4 (conflict-free).
        const int nl = wid;
        #pragma unroll
        for (int j = 0; j < 4; ++j) {
            #pragma unroll
            for (int m = 0; m < 4; ++m) {
                float lo, hi;
                unpack2(acc[j][m], lo, hi);
                sout[2 * j    ][nl][4 * lane + m] = lo;
                sout[2 * j + 1][nl][4 * lane + m] = hi;
            }
        }
    }
    __syncthreads();

    // Epilogue: 1024 (bl, d) rows of 8 n each. Warp w owns rows
    // [w*128, (w+1)*128); quarter-warps handle 4 rows per iteration.
    {
        const int q  = lane >> 3;        // quarter-warp 0..3
        const int nn = lane & 7;
        #pragma unroll
        for (int it = 0; it < 32; ++it) {
            const int r  = wid * 128 + it * 4 + q;
            const int d  = r & 7;
            const int bl = r >> 3;
            const float v = sout[d][nn][bl];
            out[((size_t)(b0 + bl) * C_OUT_ + d) * N_ + n0 + nn] = v;
        }
    }
}

extern "C" void kernel_launch(void* const* d_in, const int* in_sizes, int n_in,
                              void* d_out, int out_size)
{
    const float* x       = (const float*)d_in[0];   // (B, C_IN, N) f32
    const int*   nbr     = (const int*)  d_in[1];   // (N, K) i32
    const int*   sub_ids = (const int*)  d_in[2];   // (N,) i32
    const float* weight  = (const float*)d_in[3];   // (S, C_IN, K, C_OUT) f32
    const float* bias    = (const float*)d_in[4];   // (S, C_OUT) f32
    float*       out     = (float*)d_out;           // (B, C_OUT, N) f32

    dim3 tgrid(N_ / 128, B_ / 32, C_IN_);
    dim3 tblk(32, 8);
    transpose_x_kernel<<<tgrid, tblk>>>(x);

    dim3 mgrid(N_ / NT, B_ / BT);
    lattice_main_kernel<<<mgrid, 256>>>(nbr, sub_ids, weight, bias, out);
}

// round 10
// speedup vs baseline: 1.4958x; 1.4958x over previous
#include <cuda_runtime.h>

// Problem constants
#define B_     256
#define C_IN_  8
#define N_     4096
#define K_     9
#define S_     2
#define C_OUT_ 8

#define NB_    (N_ * B_)

#define WPAIRS_PER_CK 4    // C_OUT/2 f32x2 pairs per (s,c,k)
#define WPAIRS_PER_S  (C_IN_ * K_ * WPAIRS_PER_CK)   // 288
#define W_ELEMS       (S_ * C_IN_ * K_ * C_OUT_)     // 1152 floats

// Main-kernel tiling: 16 n x 64 b per tile (8 warps; warp = 1 n x 64 b, 2 n serially)
#define NT  16
#define BT  64
#define SOUT_STRIDE (BT + 2)   // 66: even (float2-aligned), ≡2 mod 32 (bank spread)

#define N_TILES   ((N_ / NT) * (B_ / BT))   // 1024
#define GRID_MAIN (148 * 4)                 // one full wave: 4 CTAs x 148 SMs

// Scratch (device globals: allocation-free rule)
__device__ float g_xT[C_IN_ * N_ * B_];     // (c, n, b)  33.5 MB
__device__ unsigned g_tile_ctr;             // dynamic tile counter

__device__ __forceinline__ unsigned long long splat2(float v) {
    unsigned long long r;
    asm("mov.b64 %0, {%1, %1};" : "=l"(r) : "f"(v));
    return r;
}
__device__ __forceinline__ void fma2(unsigned long long& acc,
                                     unsigned long long a,
                                     unsigned long long b) {
    asm("fma.rn.f32x2 %0, %1, %2, %0;" : "+l"(acc) : "l"(a), "l"(b));
}
__device__ __forceinline__ void unpack2(unsigned long long v, float& lo, float& hi) {
    asm("mov.b64 {%0, %1}, %2;" : "=f"(lo), "=f"(hi) : "l"(v));
}

// ---------------------------------------------------------------------------
// K1: x (B, C_IN, N) -> g_xT (C_IN, N, B). float4 both directions.
// Also resets the main kernel's tile counter (stream-ordered before K2).
// ---------------------------------------------------------------------------
__global__ __launch_bounds__(256) void transpose_x_kernel(const float* __restrict__ x)
{
    if (blockIdx.x == 0 && blockIdx.y == 0 && blockIdx.z == 0 &&
        threadIdx.x == 0 && threadIdx.y == 0)
        g_tile_ctr = 0;

    __shared__ float tile[128][33];
    const int c  = blockIdx.z;
    const int n0 = blockIdx.x * 128;
    const int b0 = blockIdx.y * 32;
    const int tx = threadIdx.x;      // 0..31
    const int ty = threadIdx.y;      // 0..7

    #pragma unroll
    for (int j = 0; j < 4; ++j) {
        const int b = ty + 8 * j;
        const float4 v = *reinterpret_cast<const float4*>(
            x + ((size_t)(b0 + b) * C_IN_ + c) * N_ + n0 + 4 * tx);
        tile[4 * tx + 0][b] = v.x;
        tile[4 * tx + 1][b] = v.y;
        tile[4 * tx + 2][b] = v.z;
        tile[4 * tx + 3][b] = v.w;
    }
    __syncthreads();

    const int tid = ty * 32 + tx;
    #pragma unroll
    for (int j = 0; j < 4; ++j) {
        const int g = j * 256 + tid;
        const int n = g >> 3;
        const int q = g & 7;
        float4 v;
        v.x = tile[n][4 * q + 0];
        v.y = tile[n][4 * q + 1];
        v.z = tile[n][4 * q + 2];
        v.w = tile[n][4 * q + 3];
        *reinterpret_cast<float4*>(
            g_xT + ((size_t)c * N_ + n0 + n) * B_ + b0 + 4 * q) = v;
    }
}

// ---------------------------------------------------------------------------
// K2: fused main compute + output transpose, persistent CTAs.
// R8 body (warp = 1n x 64b, float2 gather, smem weight broadcasts,
// k-outer/c-inner register diet, <=64 regs, 4 CTAs/SM), with tiles claimed
// dynamically from a global counter to eliminate the 1.73-wave tail.
// grid = 592 (one full wave).
// ---------------------------------------------------------------------------
__global__ __launch_bounds__(256, 4)
void lattice_main_kernel(const int*   __restrict__ nbr,
                         const int*   __restrict__ sub_ids,
                         const float* __restrict__ weight,
                         const float* __restrict__ bias,
                         float*       __restrict__ out)
{
    __shared__ __align__(16) unsigned long long sw[S_ * WPAIRS_PER_S]; // 4608 B
    __shared__ __align__(16) unsigned long long sb[S_ * WPAIRS_PER_CK];
    __shared__ float sout[C_OUT_][NT][SOUT_STRIDE];                     // 33.8 KB
    __shared__ unsigned s_tile;

    const int tid  = threadIdx.x;
    const int lane = tid & 31;
    const int wid  = tid >> 5;

    {   // weight layout (s,c,k,d) is d-innermost -> raw copy = packed f32x2
        float* swf = reinterpret_cast<float*>(sw);
        #pragma unroll
        for (int i = tid; i < W_ELEMS; i += 256) swf[i] = weight[i];
        float* sbf = reinterpret_cast<float*>(sb);
        if (tid < S_ * C_OUT_) sbf[tid] = bias[tid];
    }

    for (;;) {
        if (tid == 0) s_tile = atomicAdd(&g_tile_ctr, 1u);
        __syncthreads();                 // also orders smem weight init (1st iter)
        const unsigned t = s_tile;
        if (t >= N_TILES) break;

        const int n0 = (int)(t >> 2) * NT;     // 256 n-tiles
        const int b0 = (int)(t & 3) * BT;      // 4 b-tiles
        const float* xb = g_xT + b0 + 2 * lane;

        #pragma unroll 1
        for (int i = 0; i < 2; ++i) {
            const int nl = wid * 2 + i;
            const int n  = n0 + nl;
            const int s  = __ldg(&sub_ids[n]);   // uniform across warp

            // accA: b = b0+2*lane ; accB: b = b0+2*lane+1.
            // Pair j holds d=2j (lo), 2j+1 (hi).
            unsigned long long accA0 = sb[s * WPAIRS_PER_CK + 0];
            unsigned long long accA1 = sb[s * WPAIRS_PER_CK + 1];
            unsigned long long accA2 = sb[s * WPAIRS_PER_CK + 2];
            unsigned long long accA3 = sb[s * WPAIRS_PER_CK + 3];
            unsigned long long accB0 = accA0, accB1 = accA1;
            unsigned long long accB2 = accA2, accB3 = accA3;

            const unsigned long long* wrow = sw + s * WPAIRS_PER_S;

            #pragma unroll
            for (int k = 0; k < K_; ++k) {
                // Single scalar neighbor offset live per k (register diet).
                const int ro = __ldg(&nbr[n * K_ + k]) * B_;   // uniform
                const float* xk = xb + ro;
                const unsigned long long* wk = wrow + k * WPAIRS_PER_CK;

                #pragma unroll
                for (int c = 0; c < C_IN_; ++c) {
                    const float2 xv = __ldg(reinterpret_cast<const float2*>(
                        xk + (size_t)c * NB_));
                    const unsigned long long x0 = splat2(xv.x);
                    const unsigned long long x1 = splat2(xv.y);
                    const unsigned long long* w4 = wk + c * (K_ * WPAIRS_PER_CK);
                    const ulonglong2 wa = *reinterpret_cast<const ulonglong2*>(w4);
                    const ulonglong2 wb = *reinterpret_cast<const ulonglong2*>(w4 + 2);
                    fma2(accA0, x0, wa.x);
                    fma2(accA1, x0, wa.y);
                    fma2(accA2, x0, wb.x);
                    fma2(accA3, x0, wb.y);
                    fma2(accB0, x1, wa.x);
                    fma2(accB1, x1, wa.y);
                    fma2(accB2, x1, wb.x);
                    fma2(accB3, x1, wb.y);
                }
            }

            // Stage: float2 stores along b at (d, nl). 8B-aligned; no conflicts.
            float aLo, aHi, bLo, bHi;
            #define STAGE(J)                                                        \
                do {                                                                \
                    unpack2(accA##J, aLo, aHi);                                     \
                    unpack2(accB##J, bLo, bHi);                                     \
                    *reinterpret_cast<float2*>(&sout[2*(J)    ][nl][2*lane]) =      \
                        make_float2(aLo, bLo);                                      \
                    *reinterpret_cast<float2*>(&sout[2*(J) + 1][nl][2*lane]) =      \
                        make_float2(aHi, bHi);                                      \
                } while (0)
            STAGE(0); STAGE(1); STAGE(2); STAGE(3);
            #undef STAGE
        }
        __syncthreads();

        // Epilogue: warp w owns d = w. Half-warp 0 -> even bl, 1 -> odd bl
        // (disjoint bank parity classes); 16 consecutive n per store row.
        {
            const int d  = wid;
            const int h  = lane >> 4;        // 0 or 1
            const int nn = lane & 15;
            #pragma unroll
            for (int p = 0; p < 32; ++p) {
                const int bl = 2 * p + h;
                const float v = sout[d][nn][bl];
                out[((size_t)(b0 + bl) * C_OUT_ + d) * N_ + n0 + nn] = v;
            }
        }
        __syncthreads();   // protect sout & s_tile reuse before next tile
    }
}

extern "C" void kernel_launch(void* const* d_in, const int* in_sizes, int n_in,
                              void* d_out, int out_size)
{
    const float* x       = (const float*)d_in[0];   // (B, C_IN, N) f32
    const int*   nbr     = (const int*)  d_in[1];   // (N, K) i32
    const int*   sub_ids = (const int*)  d_in[2];   // (N,) i32
    const float* weight  = (const float*)d_in[3];   // (S, C_IN, K, C_OUT) f32
    const float* bias    = (const float*)d_in[4];   // (S, C_OUT) f32
    float*       out     = (float*)d_out;           // (B, C_OUT, N) f32

    dim3 tgrid(N_ / 128, B_ / 32, C_IN_);
    dim3 tblk(32, 8);
    transpose_x_kernel<<<tgrid, tblk>>>(x);

    lattice_main_kernel<<<GRID_MAIN, 256>>>(nbr, sub_ids, weight, bias, out);
}

// round 11
// speedup vs baseline: 1.6198x; 1.0829x over previous
#include <cuda_runtime.h>
#include <cuda_fp16.h>

// Problem constants
#define B_     256
#define C_IN_  8
#define N_     4096
#define K_     9
#define S_     2
#define C_OUT_ 8

#define NB_    (N_ * B_)
#define NB2_   (NB_ / 2)

#define WPAIRS_PER_CK 4    // C_OUT/2 f32x2 pairs per (s,c,k)
#define WPAIRS_PER_S  (C_IN_ * K_ * WPAIRS_PER_CK)   // 288
#define W_ELEMS       (S_ * C_IN_ * K_ * C_OUT_)     // 1152 floats

// Main-kernel tiling: 16 n x 64 b per block (8 warps; warp = 1 n x 64 b, 2 n serially)
#define NT  16
#define BT  64
#define SOUT_STRIDE (BT + 2)   // 66: even (float2-aligned), ≡2 mod 32 (bank spread)

// Scratch (device global: allocation-free rule). x transposed AND fp16-quantized:
// (c, n, b) with b innermost, stored as half2 pairs over b.
__device__ __half2 g_xT2[C_IN_ * N_ * B_ / 2];   // 16.8 MB

__device__ __forceinline__ unsigned long long splat2(float v) {
    unsigned long long r;
    asm("mov.b64 %0, {%1, %1};" : "=l"(r) : "f"(v));
    return r;
}
__device__ __forceinline__ void fma2(unsigned long long& acc,
                                     unsigned long long a,
                                     unsigned long long b) {
    asm("fma.rn.f32x2 %0, %1, %2, %0;" : "+l"(acc) : "l"(a), "l"(b));
}
__device__ __forceinline__ void unpack2(unsigned long long v, float& lo, float& hi) {
    asm("mov.b64 {%0, %1}, %2;" : "=f"(lo), "=f"(hi) : "l"(v));
}

// ---------------------------------------------------------------------------
// K1: x (B, C_IN, N) f32 -> g_xT2 (C_IN, N, B) fp16. float4 loads, 16B stores.
// Tile: 128 n x 32 b per block. grid (N/128, B/32, C_IN), block (32, 8).
// ---------------------------------------------------------------------------
__global__ __launch_bounds__(256) void transpose_x_kernel(const float* __restrict__ x)
{
    __shared__ float tile[128][33];
    const int c  = blockIdx.z;
    const int n0 = blockIdx.x * 128;
    const int b0 = blockIdx.y * 32;
    const int tx = threadIdx.x;      // 0..31
    const int ty = threadIdx.y;      // 0..7

    #pragma unroll
    for (int j = 0; j < 4; ++j) {
        const int b = ty + 8 * j;
        const float4 v = *reinterpret_cast<const float4*>(
            x + ((size_t)(b0 + b) * C_IN_ + c) * N_ + n0 + 4 * tx);
        tile[4 * tx + 0][b] = v.x;
        tile[4 * tx + 1][b] = v.y;
        tile[4 * tx + 2][b] = v.z;
        tile[4 * tx + 3][b] = v.w;
    }
    __syncthreads();

    // Store: each thread emits 8 b (4 half2 = 16B) per iteration.
    // g = j*256 + tid ; n = g/4 ; q = g%4 (8-b group). Conflict-free reads:
    // bank(n*33 + 8q) = (n + 8q) mod 32, all distinct within a warp.
    const int tid = ty * 32 + tx;
    #pragma unroll
    for (int j = 0; j < 2; ++j) {
        const int g = j * 256 + tid;
        const int n = g >> 2;
        const int q = g & 3;
        __half2 h[4];
        #pragma unroll
        for (int m = 0; m < 4; ++m)
            h[m] = __floats2half2_rn(tile[n][8 * q + 2 * m],
                                     tile[n][8 * q + 2 * m + 1]);
        *reinterpret_cast<uint4*>(
            g_xT2 + ((size_t)c * N_ + n0 + n) * (B_ / 2) + (b0 + 8 * q) / 2) =
            *reinterpret_cast<const uint4*>(h);
    }
}

// ---------------------------------------------------------------------------
// K2: fused main compute + output transpose (R8 body, fp16 gather).
// Block = 256 threads = 8 warps, tile = 16 n x 64 b.
// Warp w: n_local in {2w, 2w+1} (serial); lane covers the b-pair
// (b0 + 2*lane, b0 + 2*lane + 1) via ONE half2 gather load (1 wavefront).
// Weights f32 in smem (broadcast LDS.128). Accumulation all-f32.
// k-outer / c-inner register diet: <=64 regs, 4 CTAs/SM.
// grid (N/16, B/64) = 1024 blocks.
// ---------------------------------------------------------------------------
__global__ __launch_bounds__(256, 4)
void lattice_main_kernel(const int*   __restrict__ nbr,
                         const int*   __restrict__ sub_ids,
                         const float* __restrict__ weight,
                         const float* __restrict__ bias,
                         float*       __restrict__ out)
{
    __shared__ __align__(16) unsigned long long sw[S_ * WPAIRS_PER_S]; // 4608 B
    __shared__ __align__(16) unsigned long long sb[S_ * WPAIRS_PER_CK];
    __shared__ float sout[C_OUT_][NT][SOUT_STRIDE];                     // 33.8 KB

    const int tid  = threadIdx.x;
    const int lane = tid & 31;
    const int wid  = tid >> 5;

    {   // weight layout (s,c,k,d) is d-innermost -> raw copy = packed f32x2
        float* swf = reinterpret_cast<float*>(sw);
        #pragma unroll
        for (int i = tid; i < W_ELEMS; i += 256) swf[i] = weight[i];
        float* sbf = reinterpret_cast<float*>(sb);
        if (tid < S_ * C_OUT_) sbf[tid] = bias[tid];
    }
    __syncthreads();

    const int n0 = blockIdx.x * NT;
    const int b0 = blockIdx.y * BT;
    // half2 base covering the b-pair (b0 + 2*lane, b0 + 2*lane + 1)
    const __half2* xb = g_xT2 + (b0 / 2) + lane;

    #pragma unroll 1
    for (int i = 0; i < 2; ++i) {
        const int nl = wid * 2 + i;
        const int n  = n0 + nl;
        const int s  = __ldg(&sub_ids[n]);   // uniform across warp

        // accA: b = b0+2*lane ; accB: b = b0+2*lane+1. Pair j holds d=2j (lo), 2j+1 (hi).
        unsigned long long accA0 = sb[s * WPAIRS_PER_CK + 0];
        unsigned long long accA1 = sb[s * WPAIRS_PER_CK + 1];
        unsigned long long accA2 = sb[s * WPAIRS_PER_CK + 2];
        unsigned long long accA3 = sb[s * WPAIRS_PER_CK + 3];
        unsigned long long accB0 = accA0, accB1 = accA1;
        unsigned long long accB2 = accA2, accB3 = accA3;

        const unsigned long long* wrow = sw + s * WPAIRS_PER_S;

        #pragma unroll
        for (int k = 0; k < K_; ++k) {
            // Single scalar neighbor offset live per k (register diet).
            const int ro = __ldg(&nbr[n * K_ + k]) * (B_ / 2);   // uniform, half2 units
            const __half2* xk = xb + ro;
            const unsigned long long* wk = wrow + k * WPAIRS_PER_CK;

            #pragma unroll
            for (int c = 0; c < C_IN_; ++c) {
                const __half2 xh = __ldg(xk + (size_t)c * NB2_);  // 128B line: 1 wf
                const float2 xf = __half22float2(xh);
                const unsigned long long x0 = splat2(xf.x);
                const unsigned long long x1 = splat2(xf.y);
                const unsigned long long* w4 = wk + c * (K_ * WPAIRS_PER_CK);
                const ulonglong2 wa = *reinterpret_cast<const ulonglong2*>(w4);     // bcast
                const ulonglong2 wb = *reinterpret_cast<const ulonglong2*>(w4 + 2); // bcast
                fma2(accA0, x0, wa.x);
                fma2(accA1, x0, wa.y);
                fma2(accA2, x0, wb.x);
                fma2(accA3, x0, wb.y);
                fma2(accB0, x1, wa.x);
                fma2(accB1, x1, wa.y);
                fma2(accB2, x1, wb.x);
                fma2(accB3, x1, wb.y);
            }
        }

        // Stage: float2 stores along b at (d, nl). 8B-aligned; sequential -> no conflicts.
        float aLo, aHi, bLo, bHi;
        #define STAGE(J)                                                            \
            do {                                                                    \
                unpack2(accA##J, aLo, aHi);                                         \
                unpack2(accB##J, bLo, bHi);                                         \
                *reinterpret_cast<float2*>(&sout[2*(J)    ][nl][2*lane]) =          \
                    make_float2(aLo, bLo);                                          \
                *reinterpret_cast<float2*>(&sout[2*(J) + 1][nl][2*lane]) =          \
                    make_float2(aHi, bHi);                                          \
            } while (0)
        STAGE(0); STAGE(1); STAGE(2); STAGE(3);
        #undef STAGE
    }
    __syncthreads();

    // Epilogue: warp w owns d = w. Iteration p: half-warp 0 -> bl = 2p,
    // half-warp 1 -> bl = 2p+1 (even/odd -> disjoint bank parity classes).
    // Each half-warp stores 16 consecutive n (64B line) to out.
    {
        const int d  = wid;
        const int h  = lane >> 4;        // 0 or 1
        const int nn = lane & 15;
        #pragma unroll
        for (int p = 0; p < 32; ++p) {
            const int bl = 2 * p + h;
            const float v = sout[d][nn][bl];
            out[((size_t)(b0 + bl) * C_OUT_ + d) * N_ + n0 + nn] = v;
        }
    }
}

extern "C" void kernel_launch(void* const* d_in, const int* in_sizes, int n_in,
                              void* d_out, int out_size)
{
    const float* x       = (const float*)d_in[0];   // (B, C_IN, N) f32
    const int*   nbr     = (const int*)  d_in[1];   // (N, K) i32
    const int*   sub_ids = (const int*)  d_in[2];   // (N,) i32
    const float* weight  = (const float*)d_in[3];   // (S, C_IN, K, C_OUT) f32
    const float* bias    = (const float*)d_in[4];   // (S, C_OUT) f32
    float*       out     = (float*)d_out;           // (B, C_OUT, N) f32

    dim3 tgrid(N_ / 128, B_ / 32, C_IN_);
    dim3 tblk(32, 8);
    transpose_x_kernel<<<tgrid, tblk>>>(x);

    dim3 mgrid(N_ / NT, B_ / BT);
    lattice_main_kernel<<<mgrid, 256>>>(nbr, sub_ids, weight, bias, out);
}